// round 5
// baseline (speedup 1.0000x reference)
#include <cuda_runtime.h>
#include <cuda_bf16.h>
#include <cstdint>

#define EN    262144
#define NCTA  2048          // 128 rows per CTA
#define NTH   512

// ---------- frag-packed weights (filled once by pack kernel) ----------
// W1: 24 tiles (chunk*6+slice), tile=[64k x 128n]: entry 16B = {hi.r0,hi.r1,lo.r0,lo.r1}
__device__ __align__(128) unsigned char g_W1p[24 * 32768];   // 768 KB
// W2: 8 tiles (chunk*2+kslice), same format
__device__ __align__(128) unsigned char g_W2p[8 * 32768];    // 256 KB

// ---------- smem layout ----------
#define SM_A0   1024        // A frag buf 0: hi 16KB + lo 16KB
#define SM_A1   33792
#define SM_W10  66560
#define SM_W11  99328
#define SM_W2   132096      // W2 chunk (2 k-slices, 64KB)
#define SM_XS   197632      // xstage (GEMM1) / H-frag (GEMM2) overlay, 32KB
#define SM_TOT  230400

#define SW128(o) ((o) ^ (((o) >> 3) & 0x70))

// ---------- PTX helpers ----------
__device__ __forceinline__ uint32_t smem_u32(const void* p) {
    uint32_t a;
    asm("{ .reg .u64 t; cvta.to.shared.u64 t, %1; cvt.u32.u64 %0, t; }" : "=r"(a) : "l"(p));
    return a;
}
#define MBAR_INIT(a, n)   asm volatile("mbarrier.init.shared.b64 [%0], %1;" :: "r"(a), "r"(n) : "memory")
#define MBAR_EXPECT(a, b) asm volatile("mbarrier.arrive.expect_tx.shared.b64 _, [%0], %1;" :: "r"(a), "r"(b) : "memory")
#define MBAR_WAIT(a, ph) do { \
    uint32_t _m = (a), _p = (ph), _d; \
    asm volatile("{ .reg .pred p; mbarrier.try_wait.parity.acquire.cta.shared::cta.b64 p, [%1], %2; selp.b32 %0,1,0,p; }" \
        : "=r"(_d) : "r"(_m), "r"(_p) : "memory"); \
    if (!_d) { \
        asm volatile("{ .reg .pred P1; WL_%=: mbarrier.try_wait.parity.acquire.cta.shared::cta.b64 P1, [%0], %1, 0x989680;\n\t" \
                     "@P1 bra.uni WD_%=; bra.uni WL_%=; WD_%=: }" :: "r"(_m), "r"(_p) : "memory"); \
    } } while (0)

__device__ __forceinline__ void bulk_g2s(uint32_t dst, const void* src, uint32_t bytes, uint32_t bar) {
    asm volatile("cp.async.bulk.shared::cluster.global.mbarrier::complete_tx::bytes [%0], [%1], %2, [%3];"
        :: "r"(dst), "l"(src), "r"(bytes), "r"(bar) : "memory");
}
__device__ __forceinline__ void cpasync16(uint32_t dst, const void* src) {
    asm volatile("cp.async.cg.shared.global [%0], [%1], 16;" :: "r"(dst), "l"(src));
}
#define CP_COMMIT() asm volatile("cp.async.commit_group;" ::: "memory")
#define CP_WAIT0()  asm volatile("cp.async.wait_group 0;" ::: "memory")

// pack two fp32 -> bf16x2, v0 (lower k) in low 16 bits
__device__ __forceinline__ uint32_t pack2(float v0, float v1) {
    uint32_t r;
    asm("cvt.rn.bf16x2.f32 %0, %1, %2;" : "=r"(r) : "f"(v1), "f"(v0));
    return r;
}
__device__ __forceinline__ void mma_bf16(float* c, const uint4& a, uint32_t b0, uint32_t b1) {
    asm volatile("mma.sync.aligned.m16n8k16.row.col.f32.bf16.bf16.f32 "
        "{%0,%1,%2,%3}, {%4,%5,%6,%7}, {%8,%9}, {%0,%1,%2,%3};"
        : "+f"(c[0]), "+f"(c[1]), "+f"(c[2]), "+f"(c[3])
        : "r"(a.x), "r"(a.y), "r"(a.z), "r"(a.w), "r"(b0), "r"(b1));
}
// hi/lo split of a float2 -> packed bf16x2 pair
__device__ __forceinline__ void split2(float2 v, uint32_t& hi, uint32_t& lo) {
    __nv_bfloat16 h0 = __float2bfloat16(v.x), h1 = __float2bfloat16(v.y);
    hi = pack2(v.x, v.y);
    lo = pack2(v.x - __bfloat162float(h0), v.y - __bfloat162float(h1));
}

// convert one 16B A-frag entry from staged fp32 x slice (conflict-free STS.128)
__device__ __forceinline__ void conv_entry(char* Abuf, const char* xstage, int e) {
    const int mt = e >> 7, kt = (e >> 5) & 3, lane = e & 31;
    const int r0 = mt * 16 + (lane >> 2);
    const int c0 = kt * 16 + (lane & 3) * 2;
    float2 v00 = *(const float2*)(xstage + SW128((uint32_t)(r0 * 256 + c0 * 4)));
    float2 v10 = *(const float2*)(xstage + SW128((uint32_t)((r0 + 8) * 256 + c0 * 4)));
    float2 v01 = *(const float2*)(xstage + SW128((uint32_t)(r0 * 256 + (c0 + 8) * 4)));
    float2 v11 = *(const float2*)(xstage + SW128((uint32_t)((r0 + 8) * 256 + (c0 + 8) * 4)));
    uint4 hi, lo;
    split2(v00, hi.x, lo.x);
    split2(v10, hi.y, lo.y);
    split2(v01, hi.z, lo.z);
    split2(v11, hi.w, lo.w);
    *(uint4*)(Abuf + (uint32_t)e * 16)         = hi;
    *(uint4*)(Abuf + 16384 + (uint32_t)e * 16) = lo;
}

// ---------- merged pack kernel (frag-order weights, hi/lo interleaved 16B) ----------
__global__ void pack_w(const float* __restrict__ W1, const float* __restrict__ W2) {
    int idx = blockIdx.x * blockDim.x + threadIdx.x;   // 0..131071
    if (idx < 98304) {           // W1: kp*512 + n
        int kp = idx >> 9, n = idx & 511, k = kp * 2;
        float v0 = W1[(size_t)k * 512 + n], v1 = W1[(size_t)(k + 1) * 512 + n];
        uint32_t hi, lo; split2(make_float2(v0, v1), hi, lo);
        int chunk = n >> 7, slice = k >> 6;
        int kt = (k & 63) >> 4, kr = k & 15, reg = kr >> 3, nt = (n & 127) >> 3;
        int lane = (n & 7) * 4 + ((kr & 7) >> 1);
        size_t off = (size_t)(chunk * 6 + slice) * 32768
                   + (size_t)((kt * 16 + nt) * 32 + lane) * 16 + reg * 4;
        *(uint32_t*)(g_W1p + off)     = hi;
        *(uint32_t*)(g_W1p + off + 8) = lo;
    } else {                     // W2: kp*128 + n
        int j = idx - 98304;
        int kp = j >> 7, n = j & 127, k = kp * 2;
        float v0 = W2[(size_t)k * 128 + n], v1 = W2[(size_t)(k + 1) * 128 + n];
        uint32_t hi, lo; split2(make_float2(v0, v1), hi, lo);
        int chunk = k >> 7, ksl = (k >> 6) & 1;
        int kt = (k & 63) >> 4, kr = k & 15, reg = kr >> 3, nt = n >> 3;
        int lane = (n & 7) * 4 + ((kr & 7) >> 1);
        size_t off = (size_t)(chunk * 2 + ksl) * 32768
                   + (size_t)((kt * 16 + nt) * 32 + lane) * 16 + reg * 4;
        *(uint32_t*)(g_W2p + off)     = hi;
        *(uint32_t*)(g_W2p + off + 8) = lo;
    }
}

// ---------- main kernel ----------
__global__ void __launch_bounds__(NTH, 1) edge_mlp_hmma(
    const float* __restrict__ x_i, const float* __restrict__ x_j,
    const float* __restrict__ edge,
    const float* __restrict__ b1, const float* __restrict__ b2,
    const float* __restrict__ gamma, const float* __restrict__ beta,
    float* __restrict__ out)
{
    extern __shared__ char smem[];
    const uint32_t sb = smem_u32(smem);
    const int tid  = threadIdx.x;
    const int w    = tid >> 5, lane = tid & 31;
    const int mband = w >> 2, nband = w & 3;
    const int row0 = blockIdx.x * 128;

    if (tid == 0) { MBAR_INIT(sb + 0, 1); MBAR_INIT(sb + 8, 1); MBAR_INIT(sb + 16, 1); }
    __syncthreads();

    float acc1[2][4][4];
    float acc2[2][4][4];
#pragma unroll
    for (int a = 0; a < 2; a++)
#pragma unroll
        for (int b = 0; b < 4; b++)
#pragma unroll
            for (int cc = 0; cc < 4; cc++) { acc1[a][b][cc] = 0.f; acc2[a][b][cc] = 0.f; }

    int p0 = 0, p1 = 0, pw = 0;

    // prologue: W1 slice0 bulk; stage x_i k0..63; convert slice0 into A0
    if (tid == 0) { MBAR_EXPECT(sb + 0, 32768); bulk_g2s(sb + SM_W10, g_W1p, 32768, sb + 0); }
    {
#pragma unroll
        for (int ww = 0; ww < 4; ww++) {
            int v = tid + ww * NTH;
            int r = v >> 4, u = v & 15;
            cpasync16(sb + SM_XS + SW128((uint32_t)(r * 256 + u * 16)),
                      x_i + (size_t)(row0 + r) * 128 + u * 4);
        }
        CP_COMMIT(); CP_WAIT0();
        __syncthreads();
        conv_entry(smem + SM_A0, smem + SM_XS, tid);
        conv_entry(smem + SM_A0, smem + SM_XS, tid + NTH);
    }
    __syncthreads();

#pragma unroll 1
    for (int c = 0; c < 4; c++) {
        if (tid == 0) { MBAR_EXPECT(sb + 16, 65536); bulk_g2s(sb + SM_W2, g_W2p + (size_t)c * 65536, 65536, sb + 16); }

        // ===== GEMM1: 6 k-slices of 64 =====
#pragma unroll 1
        for (int sl = 0; sl < 6; sl++) {
            const int s = c * 6 + sl;
            if (tid == 0 && s < 23) {
                uint32_t bar = sb + (((s + 1) & 1) ? 8 : 0);
                uint32_t dst = sb + (((s + 1) & 1) ? SM_W11 : SM_W10);
                MBAR_EXPECT(bar, 32768);
                bulk_g2s(dst, g_W1p + (size_t)(s + 1) * 32768, 32768, bar);
            }
            // stage raw x for slice s+1
            if (s < 23) {
                int sl2 = (s + 1) % 6;
                const float* xs = (sl2 < 2) ? x_i : (sl2 < 4) ? x_j : edge;
                int koff = (sl2 & 1) * 64;
#pragma unroll
                for (int ww = 0; ww < 4; ww++) {
                    int v = tid + ww * NTH;
                    int r = v >> 4, u = v & 15;
                    cpasync16(sb + SM_XS + SW128((uint32_t)(r * 256 + u * 16)),
                              xs + (size_t)(row0 + r) * 128 + koff + u * 4);
                }
                CP_COMMIT();
            }
            // wait W1 slice s
            if (s & 1) { MBAR_WAIT(sb + 8, p1); p1 ^= 1; }
            else       { MBAR_WAIT(sb + 0, p0); p0 ^= 1; }

            const char* Ab = smem + ((s & 1) ? SM_A1 : SM_A0);
            const char* Wb = smem + ((s & 1) ? SM_W11 : SM_W10);
#pragma unroll
            for (int kt = 0; kt < 4; kt++) {
                uint4 ah[2], al[2];
#pragma unroll
                for (int m = 0; m < 2; m++) {
                    uint32_t aoff = (uint32_t)(((mband * 2 + m) * 4 + kt) * 32 + lane) * 16;
                    ah[m] = *(const uint4*)(Ab + aoff);
                    al[m] = *(const uint4*)(Ab + 16384 + aoff);
                }
#pragma unroll
                for (int ntp = 0; ntp < 4; ntp++) {
                    int nt = nband * 4 + ntp;
                    uint4 Bv = *(const uint4*)(Wb + (uint32_t)((kt * 16 + nt) * 32 + lane) * 16);
                    mma_bf16(acc1[0][ntp], ah[0], Bv.x, Bv.y);
                    mma_bf16(acc1[1][ntp], ah[1], Bv.x, Bv.y);
                    mma_bf16(acc1[0][ntp], ah[0], Bv.z, Bv.w);
                    mma_bf16(acc1[1][ntp], ah[1], Bv.z, Bv.w);
                    mma_bf16(acc1[0][ntp], al[0], Bv.x, Bv.y);
                    mma_bf16(acc1[1][ntp], al[1], Bv.x, Bv.y);
                }
            }
            CP_WAIT0();
            __syncthreads();          // staging visible; MMAs done reading A
            if (s < 23) {
                char* Ab2 = smem + (((s + 1) & 1) ? SM_A1 : SM_A0);
                conv_entry(Ab2, smem + SM_XS, tid);
                conv_entry(Ab2, smem + SM_XS, tid + NTH);
            }
            __syncthreads();          // conversion visible before next MMA
        }

        // ===== SiLU -> h frags; GEMM2 over 2 k-slices of 64 =====
#pragma unroll 1
        for (int ksl = 0; ksl < 2; ksl++) {
            if ((nband >> 1) == ksl) {
#pragma unroll
                for (int ntp = 0; ntp < 4; ntp++) {
                    int colc = nband * 32 + ntp * 8 + (lane & 3) * 2;
                    int colg = c * 128 + colc;
                    float bb0 = b1[colg], bb1 = b1[colg + 1];
                    int kloc = colc - ksl * 64;
                    int kt_h = kloc >> 4;
                    int regb = 2 * ((kloc >> 3) & 1);
#pragma unroll
                    for (int mtp = 0; mtp < 2; mtp++) {
                        uint32_t base = (uint32_t)(((mband * 2 + mtp) * 4 + kt_h) * 32 + lane) * 16;
                        uint32_t hi0, lo0, hi1, lo1;
                        float v0 = acc1[mtp][ntp][0] + bb0;
                        float v1 = acc1[mtp][ntp][1] + bb1;
                        float v2 = acc1[mtp][ntp][2] + bb0;
                        float v3 = acc1[mtp][ntp][3] + bb1;
                        v0 = v0 / (1.0f + __expf(-v0));
                        v1 = v1 / (1.0f + __expf(-v1));
                        v2 = v2 / (1.0f + __expf(-v2));
                        v3 = v3 / (1.0f + __expf(-v3));
                        split2(make_float2(v0, v1), hi0, lo0);
                        split2(make_float2(v2, v3), hi1, lo1);
                        *(uint2*)(smem + SM_XS + base + regb * 4)         = make_uint2(hi0, hi1);
                        *(uint2*)(smem + SM_XS + 16384 + base + regb * 4) = make_uint2(lo0, lo1);
                    }
                }
            }
            if (ksl == 0) { MBAR_WAIT(sb + 16, pw); pw ^= 1; }
            __syncthreads();

            const char* Hb  = smem + SM_XS;
            const char* W2b = smem + SM_W2 + ksl * 32768;
#pragma unroll
            for (int kt = 0; kt < 4; kt++) {
                uint4 ah[2], al[2];
#pragma unroll
                for (int m = 0; m < 2; m++) {
                    uint32_t aoff = (uint32_t)(((mband * 2 + m) * 4 + kt) * 32 + lane) * 16;
                    ah[m] = *(const uint4*)(Hb + aoff);
                    al[m] = *(const uint4*)(Hb + 16384 + aoff);
                }
#pragma unroll
                for (int ntp = 0; ntp < 4; ntp++) {
                    int nt = nband * 4 + ntp;
                    uint4 Bv = *(const uint4*)(W2b + (uint32_t)((kt * 16 + nt) * 32 + lane) * 16);
                    mma_bf16(acc2[0][ntp], ah[0], Bv.x, Bv.y);
                    mma_bf16(acc2[1][ntp], ah[1], Bv.x, Bv.y);
                    mma_bf16(acc2[0][ntp], ah[0], Bv.z, Bv.w);
                    mma_bf16(acc2[1][ntp], ah[1], Bv.z, Bv.w);
                    mma_bf16(acc2[0][ntp], al[0], Bv.x, Bv.y);
                    mma_bf16(acc2[1][ntp], al[1], Bv.x, Bv.y);
                }
            }
            __syncthreads();
        }
        // reset acc1 for next chunk
#pragma unroll
        for (int a = 0; a < 2; a++)
#pragma unroll
            for (int b = 0; b < 4; b++)
#pragma unroll
                for (int cc = 0; cc < 4; cc++) acc1[a][b][cc] = 0.f;
    }

    // ===== epilogue: stage acc2+b2, LayerNorm, +edge, store =====
    float* stg = (float*)(smem + SM_A0);   // 128 x 130 fp32 (A/W1 regions dead)
    __syncthreads();
#pragma unroll
    for (int ntp = 0; ntp < 4; ntp++) {
        int col = nband * 32 + ntp * 8 + (lane & 3) * 2;
        float bb0 = b2[col], bb1 = b2[col + 1];
#pragma unroll
        for (int mtp = 0; mtp < 2; mtp++) {
            int row = mband * 32 + mtp * 16 + (lane >> 2);
            float2 v0 = make_float2(acc2[mtp][ntp][0] + bb0, acc2[mtp][ntp][1] + bb1);
            float2 v1 = make_float2(acc2[mtp][ntp][2] + bb0, acc2[mtp][ntp][3] + bb1);
            *(float2*)(stg + row * 130 + col)       = v0;
            *(float2*)(stg + (row + 8) * 130 + col) = v1;
        }
    }
    __syncthreads();
    if (tid < 128) {
        float* rp = stg + tid * 130;
        float s = 0.f, qq = 0.f;
#pragma unroll
        for (int j = 0; j < 128; j += 2) {
            float2 v = *(float2*)(rp + j);
            s += v.x + v.y;
            qq += v.x * v.x + v.y * v.y;
        }
        float mu = s * (1.0f / 128.0f);
        float var = qq * (1.0f / 128.0f) - mu * mu;
        float rs = rsqrtf(var + 1e-5f);
#pragma unroll
        for (int j = 0; j < 128; j += 2) {
            float2 v = *(float2*)(rp + j);
            float2 g = *(const float2*)(gamma + j);
            float2 b = *(const float2*)(beta + j);
            v.x = (v.x - mu) * rs * g.x + b.x;
            v.y = (v.y - mu) * rs * g.y + b.y;
            *(float2*)(rp + j) = v;
        }
    }
    __syncthreads();
#pragma unroll
    for (int it = 0; it < 8; it++) {
        int idx = tid + it * NTH;
        int r = idx >> 5, c4 = idx & 31;
        float2 u0 = *(float2*)(stg + r * 130 + c4 * 4);
        float2 u1 = *(float2*)(stg + r * 130 + c4 * 4 + 2);
        float4 e = *(const float4*)(edge + (size_t)(row0 + r) * 128 + c4 * 4);
        float4 o = make_float4(u0.x + e.x, u0.y + e.y, u1.x + e.z, u1.y + e.w);
        *(float4*)(out + (size_t)(row0 + r) * 128 + c4 * 4) = o;
    }
}

extern "C" void kernel_launch(void* const* d_in, const int* in_sizes, int n_in,
                              void* d_out, int out_size)
{
    const float* x_i   = (const float*)d_in[0];
    const float* x_j   = (const float*)d_in[1];
    const float* edge  = (const float*)d_in[2];
    const float* W1    = (const float*)d_in[3];
    const float* b1    = (const float*)d_in[4];
    const float* W2    = (const float*)d_in[5];
    const float* b2    = (const float*)d_in[6];
    const float* gamma = (const float*)d_in[7];
    const float* beta  = (const float*)d_in[8];
    float* out = (float*)d_out;

    cudaFuncSetAttribute(edge_mlp_hmma, cudaFuncAttributeMaxDynamicSharedMemorySize, SM_TOT);

    pack_w<<<512, 256>>>(W1, W2);
    edge_mlp_hmma<<<NCTA, NTH, SM_TOT>>>(x_i, x_j, edge, b1, b2, gamma, beta, out);
}

// round 6
// speedup vs baseline: 1.9107x; 1.9107x over previous
#include <cuda_runtime.h>
#include <cuda_fp16.h>
#include <cstdint>

#define EN    262144
#define NCTA  2048          // 128 rows per CTA
#define NTH   512

// ---------- frag-packed fp16 weights (filled once by pack kernel) ----------
// W1: 24 tiles (chunk*6+slice), tile=[64k x 128n] fp16: entry 8B = {r0,r1}, 16KB/tile
__device__ __align__(128) unsigned char g_W1p[24 * 16384];   // 384 KB
// W2: 8 tiles (chunk*2+kslice), 16KB/tile
__device__ __align__(128) unsigned char g_W2p[8 * 16384];    // 128 KB

// ---------- smem layout ----------
#define SM_A0   1024        // A frag buf 0: hi 16KB + lo 16KB
#define SM_A1   33792
#define SM_W10  66560       // 16KB
#define SM_W11  82944       // 16KB
#define SM_W2   99328       // W2 chunk (2 k-slices, 32KB)
#define SM_XS0  132096      // raw x stage buf 0 (32KB)
#define SM_XS1  164864      // raw x stage buf 1 (32KB)
#define SM_H    197632      // h frag: hi 16KB + lo 16KB
#define SM_TOT  230400

#define SW128(o) ((o) ^ (((o) >> 3) & 0x70))

// ---------- PTX helpers ----------
__device__ __forceinline__ uint32_t smem_u32(const void* p) {
    uint32_t a;
    asm("{ .reg .u64 t; cvta.to.shared.u64 t, %1; cvt.u32.u64 %0, t; }" : "=r"(a) : "l"(p));
    return a;
}
#define MBAR_INIT(a, n)   asm volatile("mbarrier.init.shared.b64 [%0], %1;" :: "r"(a), "r"(n) : "memory")
#define MBAR_EXPECT(a, b) asm volatile("mbarrier.arrive.expect_tx.shared.b64 _, [%0], %1;" :: "r"(a), "r"(b) : "memory")
#define MBAR_WAIT(a, ph) do { \
    uint32_t _m = (a), _p = (ph), _d; \
    asm volatile("{ .reg .pred p; mbarrier.try_wait.parity.acquire.cta.shared::cta.b64 p, [%1], %2; selp.b32 %0,1,0,p; }" \
        : "=r"(_d) : "r"(_m), "r"(_p) : "memory"); \
    if (!_d) { \
        asm volatile("{ .reg .pred P1; WL_%=: mbarrier.try_wait.parity.acquire.cta.shared::cta.b64 P1, [%0], %1, 0x989680;\n\t" \
                     "@P1 bra.uni WD_%=; bra.uni WL_%=; WD_%=: }" :: "r"(_m), "r"(_p) : "memory"); \
    } } while (0)

__device__ __forceinline__ void bulk_g2s(uint32_t dst, const void* src, uint32_t bytes, uint32_t bar) {
    asm volatile("cp.async.bulk.shared::cluster.global.mbarrier::complete_tx::bytes [%0], [%1], %2, [%3];"
        :: "r"(dst), "l"(src), "r"(bytes), "r"(bar) : "memory");
}
__device__ __forceinline__ void cpasync16(uint32_t dst, const void* src) {
    asm volatile("cp.async.cg.shared.global [%0], [%1], 16;" :: "r"(dst), "l"(src));
}
#define CP_COMMIT() asm volatile("cp.async.commit_group;" ::: "memory")
#define CP_WAIT0()  asm volatile("cp.async.wait_group 0;" ::: "memory")
#define CP_WAIT1()  asm volatile("cp.async.wait_group 1;" ::: "memory")

// pack two fp32 -> f16x2, v0 (lower k) in low 16 bits
__device__ __forceinline__ uint32_t pack2h(float v0, float v1) {
    uint32_t r;
    asm("cvt.rn.f16x2.f32 %0, %1, %2;" : "=r"(r) : "f"(v1), "f"(v0));
    return r;
}
__device__ __forceinline__ void mma_f16(float* c, const uint4& a, uint32_t b0, uint32_t b1) {
    asm volatile("mma.sync.aligned.m16n8k16.row.col.f32.f16.f16.f32 "
        "{%0,%1,%2,%3}, {%4,%5,%6,%7}, {%8,%9}, {%0,%1,%2,%3};"
        : "+f"(c[0]), "+f"(c[1]), "+f"(c[2]), "+f"(c[3])
        : "r"(a.x), "r"(a.y), "r"(a.z), "r"(a.w), "r"(b0), "r"(b1));
}
// fp16 hi/lo split of a float2 -> packed f16x2 pair (x = hi + lo exact to ~22 bits)
__device__ __forceinline__ void split2h(float2 v, uint32_t& hi, uint32_t& lo) {
    __half h0 = __float2half_rn(v.x), h1 = __float2half_rn(v.y);
    hi = pack2h(v.x, v.y);
    lo = pack2h(v.x - __half2float(h0), v.y - __half2float(h1));
}
// convert one 16B A-frag entry from staged fp32 x slice (conflict-free STS.128)
__device__ __forceinline__ void conv_entry(char* Abuf, const char* xstage, int e) {
    const int mt = e >> 7, kt = (e >> 5) & 3, lane = e & 31;
    const int r0 = mt * 16 + (lane >> 2);
    const int c0 = kt * 16 + (lane & 3) * 2;
    float2 v00 = *(const float2*)(xstage + SW128((uint32_t)(r0 * 256 + c0 * 4)));
    float2 v10 = *(const float2*)(xstage + SW128((uint32_t)((r0 + 8) * 256 + c0 * 4)));
    float2 v01 = *(const float2*)(xstage + SW128((uint32_t)(r0 * 256 + (c0 + 8) * 4)));
    float2 v11 = *(const float2*)(xstage + SW128((uint32_t)((r0 + 8) * 256 + (c0 + 8) * 4)));
    uint4 hi, lo;
    split2h(v00, hi.x, lo.x);
    split2h(v10, hi.y, lo.y);
    split2h(v01, hi.z, lo.z);
    split2h(v11, hi.w, lo.w);
    *(uint4*)(Abuf + (uint32_t)e * 16)         = hi;
    *(uint4*)(Abuf + 16384 + (uint32_t)e * 16) = lo;
}

// ---------- pack kernel (frag-order fp16 weights) ----------
__global__ void pack_w(const float* __restrict__ W1, const float* __restrict__ W2) {
    int idx = blockIdx.x * blockDim.x + threadIdx.x;   // 0..131071
    if (idx < 98304) {           // W1: kp*512 + n
        int kp = idx >> 9, n = idx & 511, k = kp * 2;
        float v0 = W1[(size_t)k * 512 + n], v1 = W1[(size_t)(k + 1) * 512 + n];
        int chunk = n >> 7, slice = k >> 6;
        int kt = (k & 63) >> 4, kr = k & 15, reg = kr >> 3, nt = (n & 127) >> 3;
        int lane = (n & 7) * 4 + ((kr & 7) >> 1);
        size_t off = (size_t)(chunk * 6 + slice) * 16384
                   + (size_t)((kt * 16 + nt) * 32 + lane) * 8 + reg * 4;
        *(uint32_t*)(g_W1p + off) = pack2h(v0, v1);
    } else {                     // W2: kp*128 + n
        int j = idx - 98304;
        int kp = j >> 7, n = j & 127, k = kp * 2;
        float v0 = W2[(size_t)k * 128 + n], v1 = W2[(size_t)(k + 1) * 128 + n];
        int chunk = k >> 7, ksl = (k >> 6) & 1;
        int kt = (k & 63) >> 4, kr = k & 15, reg = kr >> 3, nt = n >> 3;
        int lane = (n & 7) * 4 + ((kr & 7) >> 1);
        size_t off = (size_t)(chunk * 2 + ksl) * 16384
                   + (size_t)((kt * 16 + nt) * 32 + lane) * 8 + reg * 4;
        *(uint32_t*)(g_W2p + off) = pack2h(v0, v1);
    }
}

// stage one 64-col fp32 x slice into xstage buffer via cp.async (4x16B per thread)
__device__ __forceinline__ void stage_slice(uint32_t xsbase, int ss, int row0, int tid,
                                            const float* x_i, const float* x_j,
                                            const float* edge) {
    const float* xs = (ss % 6 < 2) ? x_i : (ss % 6 < 4) ? x_j : edge;
    const int koff = (ss & 1) * 64;
#pragma unroll
    for (int ww = 0; ww < 4; ww++) {
        int v = tid + ww * NTH;
        int r = v >> 4, u = v & 15;
        cpasync16(xsbase + SW128((uint32_t)(r * 256 + u * 16)),
                  xs + (size_t)(row0 + r) * 128 + koff + u * 4);
    }
}

// ---------- main kernel ----------
__global__ void __launch_bounds__(NTH, 1) edge_mlp_hmma(
    const float* __restrict__ x_i, const float* __restrict__ x_j,
    const float* __restrict__ edge,
    const float* __restrict__ b1, const float* __restrict__ b2,
    const float* __restrict__ gamma, const float* __restrict__ beta,
    float* __restrict__ out)
{
    extern __shared__ char smem[];
    const uint32_t sb = smem_u32(smem);
    const int tid  = threadIdx.x;
    const int w    = tid >> 5, lane = tid & 31;
    const int mband = w >> 2, nband = w & 3;
    const int row0 = blockIdx.x * 128;

    if (tid == 0) { MBAR_INIT(sb + 0, 1); MBAR_INIT(sb + 8, 1); MBAR_INIT(sb + 16, 1); }
    __syncthreads();

    float acc1[2][4][4];
    float acc2[2][4][4];
#pragma unroll
    for (int a = 0; a < 2; a++)
#pragma unroll
        for (int b = 0; b < 4; b++)
#pragma unroll
            for (int cc = 0; cc < 4; cc++) { acc1[a][b][cc] = 0.f; acc2[a][b][cc] = 0.f; }

    int p0 = 0, p1 = 0, pw = 0;

    // ---- prologue: W1(0) bulk; stage x(0), x(1); convert x(0)->A0 ----
    if (tid == 0) { MBAR_EXPECT(sb + 0, 16384); bulk_g2s(sb + SM_W10, g_W1p, 16384, sb + 0); }
    stage_slice(sb + SM_XS0, 0, row0, tid, x_i, x_j, edge); CP_COMMIT();
    stage_slice(sb + SM_XS1, 1, row0, tid, x_i, x_j, edge); CP_COMMIT();
    CP_WAIT1();
    __syncthreads();
    conv_entry(smem + SM_A0, smem + SM_XS0, tid);
    conv_entry(smem + SM_A0, smem + SM_XS0, tid + NTH);
    __syncthreads();

#pragma unroll 1
    for (int c = 0; c < 4; c++) {
        if (tid == 0) { MBAR_EXPECT(sb + 16, 32768); bulk_g2s(sb + SM_W2, g_W2p + (size_t)c * 32768, 32768, sb + 16); }

        // ===== GEMM1: 6 k-slices of 64, one sync per slice =====
#pragma unroll 1
        for (int sl = 0; sl < 6; sl++) {
            const int s = c * 6 + sl;
            // stage x(s+2) into XS[s&1]
            if (s <= 21) {
                stage_slice(sb + ((s & 1) ? SM_XS1 : SM_XS0), s + 2, row0, tid, x_i, x_j, edge);
                CP_COMMIT();
                CP_WAIT1();            // x(s+1) complete
            } else {
                CP_WAIT0();
            }
            // wait W1 slice s
            if (s & 1) { MBAR_WAIT(sb + 8, p1); p1 ^= 1; }
            else       { MBAR_WAIT(sb + 0, p0); p0 ^= 1; }
            __syncthreads();   // x(s+1) visible; MMA(s-1) done; A[s&1] conversion visible
            // issue W1(s+1) bulk into the buffer MMA(s-1) just freed
            if (tid == 0 && s < 23) {
                uint32_t bar = sb + (((s + 1) & 1) ? 8 : 0);
                uint32_t dst = sb + (((s + 1) & 1) ? SM_W11 : SM_W10);
                MBAR_EXPECT(bar, 16384);
                bulk_g2s(dst, g_W1p + (size_t)(s + 1) * 16384, 16384, bar);
            }
            // convert x(s+1) -> A[(s+1)&1] (overlaps with MMA issue across warps)
            if (s < 23) {
                char* Ab2 = smem + (((s + 1) & 1) ? SM_A1 : SM_A0);
                const char* xsrc = smem + (((s + 1) & 1) ? SM_XS1 : SM_XS0);
                conv_entry(Ab2, xsrc, tid);
                conv_entry(Ab2, xsrc, tid + NTH);
            }
            // MMA slice s (2-pass fp16)
            const char* Ab = smem + ((s & 1) ? SM_A1 : SM_A0);
            const char* Wb = smem + ((s & 1) ? SM_W11 : SM_W10);
#pragma unroll
            for (int kt = 0; kt < 4; kt++) {
                uint4 ah[2], al[2];
#pragma unroll
                for (int m = 0; m < 2; m++) {
                    uint32_t aoff = (uint32_t)(((mband * 2 + m) * 4 + kt) * 32 + lane) * 16;
                    ah[m] = *(const uint4*)(Ab + aoff);
                    al[m] = *(const uint4*)(Ab + 16384 + aoff);
                }
#pragma unroll
                for (int ntp = 0; ntp < 4; ntp++) {
                    int nt = nband * 4 + ntp;
                    uint2 Bv = *(const uint2*)(Wb + (uint32_t)((kt * 16 + nt) * 32 + lane) * 8);
                    mma_f16(acc1[0][ntp], ah[0], Bv.x, Bv.y);
                    mma_f16(acc1[1][ntp], ah[1], Bv.x, Bv.y);
                    mma_f16(acc1[0][ntp], al[0], Bv.x, Bv.y);
                    mma_f16(acc1[1][ntp], al[1], Bv.x, Bv.y);
                }
            }
        }

        // ===== SiLU -> h frags (fp16 hi/lo); GEMM2 over 2 k-slices of 64 =====
#pragma unroll 1
        for (int ksl = 0; ksl < 2; ksl++) {
            if ((nband >> 1) == ksl) {
#pragma unroll
                for (int ntp = 0; ntp < 4; ntp++) {
                    int colc = nband * 32 + ntp * 8 + (lane & 3) * 2;
                    int colg = c * 128 + colc;
                    float bb0 = b1[colg], bb1 = b1[colg + 1];
                    int kloc = colc - ksl * 64;
                    int kt_h = kloc >> 4;
                    int regb = 2 * ((kloc >> 3) & 1);
#pragma unroll
                    for (int mtp = 0; mtp < 2; mtp++) {
                        uint32_t base = (uint32_t)(((mband * 2 + mtp) * 4 + kt_h) * 32 + lane) * 16;
                        float v0 = acc1[mtp][ntp][0] + bb0;
                        float v1 = acc1[mtp][ntp][1] + bb1;
                        float v2 = acc1[mtp][ntp][2] + bb0;
                        float v3 = acc1[mtp][ntp][3] + bb1;
                        v0 = v0 / (1.0f + __expf(-v0));
                        v1 = v1 / (1.0f + __expf(-v1));
                        v2 = v2 / (1.0f + __expf(-v2));
                        v3 = v3 / (1.0f + __expf(-v3));
                        uint32_t hi0, lo0, hi1, lo1;
                        split2h(make_float2(v0, v1), hi0, lo0);
                        split2h(make_float2(v2, v3), hi1, lo1);
                        *(uint2*)(smem + SM_H + base + regb * 4)         = make_uint2(hi0, hi1);
                        *(uint2*)(smem + SM_H + 16384 + base + regb * 4) = make_uint2(lo0, lo1);
                    }
                }
            }
            if (ksl == 0) { MBAR_WAIT(sb + 16, pw); pw ^= 1; }
            __syncthreads();

            const char* Hb  = smem + SM_H;
            const char* W2b = smem + SM_W2 + ksl * 16384;
#pragma unroll
            for (int kt = 0; kt < 4; kt++) {
                uint4 ah[2], al[2];
#pragma unroll
                for (int m = 0; m < 2; m++) {
                    uint32_t aoff = (uint32_t)(((mband * 2 + m) * 4 + kt) * 32 + lane) * 16;
                    ah[m] = *(const uint4*)(Hb + aoff);
                    al[m] = *(const uint4*)(Hb + 16384 + aoff);
                }
#pragma unroll
                for (int ntp = 0; ntp < 4; ntp++) {
                    int nt = nband * 4 + ntp;
                    uint2 Bv = *(const uint2*)(W2b + (uint32_t)((kt * 16 + nt) * 32 + lane) * 8);
                    mma_f16(acc2[0][ntp], ah[0], Bv.x, Bv.y);
                    mma_f16(acc2[1][ntp], ah[1], Bv.x, Bv.y);
                    mma_f16(acc2[0][ntp], al[0], Bv.x, Bv.y);
                    mma_f16(acc2[1][ntp], al[1], Bv.x, Bv.y);
                }
            }
            __syncthreads();
        }
        // reset acc1 for next chunk
#pragma unroll
        for (int a = 0; a < 2; a++)
#pragma unroll
            for (int b = 0; b < 4; b++)
#pragma unroll
                for (int cc = 0; cc < 4; cc++) acc1[a][b][cc] = 0.f;
    }

    // ===== epilogue: stage acc2+b2, LayerNorm, +edge, store =====
    float* stg = (float*)(smem + SM_A0);   // 128 x 130 fp32 (A/W1 regions dead)
    __syncthreads();
#pragma unroll
    for (int ntp = 0; ntp < 4; ntp++) {
        int col = nband * 32 + ntp * 8 + (lane & 3) * 2;
        float bb0 = b2[col], bb1 = b2[col + 1];
#pragma unroll
        for (int mtp = 0; mtp < 2; mtp++) {
            int row = mband * 32 + mtp * 16 + (lane >> 2);
            float2 v0 = make_float2(acc2[mtp][ntp][0] + bb0, acc2[mtp][ntp][1] + bb1);
            float2 v1 = make_float2(acc2[mtp][ntp][2] + bb0, acc2[mtp][ntp][3] + bb1);
            *(float2*)(stg + row * 130 + col)       = v0;
            *(float2*)(stg + (row + 8) * 130 + col) = v1;
        }
    }
    __syncthreads();
    if (tid < 128) {
        float* rp = stg + tid * 130;
        float s = 0.f, qq = 0.f;
#pragma unroll
        for (int j = 0; j < 128; j += 2) {
            float2 v = *(float2*)(rp + j);
            s += v.x + v.y;
            qq += v.x * v.x + v.y * v.y;
        }
        float mu = s * (1.0f / 128.0f);
        float var = qq * (1.0f / 128.0f) - mu * mu;
        float rs = rsqrtf(var + 1e-5f);
#pragma unroll
        for (int j = 0; j < 128; j += 2) {
            float2 v = *(float2*)(rp + j);
            float2 g = *(const float2*)(gamma + j);
            float2 b = *(const float2*)(beta + j);
            v.x = (v.x - mu) * rs * g.x + b.x;
            v.y = (v.y - mu) * rs * g.y + b.y;
            *(float2*)(rp + j) = v;
        }
    }
    __syncthreads();
#pragma unroll
    for (int it = 0; it < 8; it++) {
        int idx = tid + it * NTH;
        int r = idx >> 5, c4 = idx & 31;
        float2 u0 = *(float2*)(stg + r * 130 + c4 * 4);
        float2 u1 = *(float2*)(stg + r * 130 + c4 * 4 + 2);
        float4 e = *(const float4*)(edge + (size_t)(row0 + r) * 128 + c4 * 4);
        float4 o = make_float4(u0.x + e.x, u0.y + e.y, u1.x + e.z, u1.y + e.w);
        *(float4*)(out + (size_t)(row0 + r) * 128 + c4 * 4) = o;
    }
}

extern "C" void kernel_launch(void* const* d_in, const int* in_sizes, int n_in,
                              void* d_out, int out_size)
{
    const float* x_i   = (const float*)d_in[0];
    const float* x_j   = (const float*)d_in[1];
    const float* edge  = (const float*)d_in[2];
    const float* W1    = (const float*)d_in[3];
    const float* b1    = (const float*)d_in[4];
    const float* W2    = (const float*)d_in[5];
    const float* b2    = (const float*)d_in[6];
    const float* gamma = (const float*)d_in[7];
    const float* beta  = (const float*)d_in[8];
    float* out = (float*)d_out;

    cudaFuncSetAttribute(edge_mlp_hmma, cudaFuncAttributeMaxDynamicSharedMemorySize, SM_TOT);

    pack_w<<<512, 256>>>(W1, W2);
    edge_mlp_hmma<<<NCTA, NTH, SM_TOT>>>(x_i, x_j, edge, b1, b2, gamma, beta, out);
}

// round 7
// speedup vs baseline: 2.2585x; 1.1820x over previous
#include <cuda_runtime.h>
#include <cuda_fp16.h>
#include <cstdint>

#define EN    262144
#define NCTA  2048          // 128 rows per CTA
#define NTH   512

// ---------- frag-packed fp16 weights (filled once by pack kernel) ----------
// W1: 24 tiles (chunk*6+slice), tile=[64k x 128n] fp16, 16KB
//     entry 16B at ((kt*8+np)*32+lane)*16 = {nt=2np:r0,r1, nt=2np+1:r0,r1}
__device__ __align__(128) unsigned char g_W1p[24 * 16384];   // 384 KB
// W2: 8 tiles (chunk*2+kslice), 16KB, same format
__device__ __align__(128) unsigned char g_W2p[8 * 16384];    // 128 KB

// ---------- smem layout ----------
#define SM_A0   1024        // A frag buf 0 (16KB, fp16 single)
#define SM_A1   17408
#define SM_W10  33792       // 16KB
#define SM_W11  50176
#define SM_W2   66560       // W2 chunk (2 k-slices, 32KB)
#define SM_H    99328       // h frag (16KB)
#define SM_TOT  116736

// ---------- PTX helpers ----------
__device__ __forceinline__ uint32_t smem_u32(const void* p) {
    uint32_t a;
    asm("{ .reg .u64 t; cvta.to.shared.u64 t, %1; cvt.u32.u64 %0, t; }" : "=r"(a) : "l"(p));
    return a;
}
#define MBAR_INIT(a, n)   asm volatile("mbarrier.init.shared.b64 [%0], %1;" :: "r"(a), "r"(n) : "memory")
#define MBAR_EXPECT(a, b) asm volatile("mbarrier.arrive.expect_tx.shared.b64 _, [%0], %1;" :: "r"(a), "r"(b) : "memory")
#define MBAR_WAIT(a, ph) do { \
    uint32_t _m = (a), _p = (ph), _d; \
    asm volatile("{ .reg .pred p; mbarrier.try_wait.parity.acquire.cta.shared::cta.b64 p, [%1], %2; selp.b32 %0,1,0,p; }" \
        : "=r"(_d) : "r"(_m), "r"(_p) : "memory"); \
    if (!_d) { \
        asm volatile("{ .reg .pred P1; WL_%=: mbarrier.try_wait.parity.acquire.cta.shared::cta.b64 P1, [%0], %1, 0x989680;\n\t" \
                     "@P1 bra.uni WD_%=; bra.uni WL_%=; WD_%=: }" :: "r"(_m), "r"(_p) : "memory"); \
    } } while (0)

__device__ __forceinline__ void bulk_g2s(uint32_t dst, const void* src, uint32_t bytes, uint32_t bar) {
    asm volatile("cp.async.bulk.shared::cluster.global.mbarrier::complete_tx::bytes [%0], [%1], %2, [%3];"
        :: "r"(dst), "l"(src), "r"(bytes), "r"(bar) : "memory");
}
// pack two fp32 -> f16x2, v0 (lower k) in low 16 bits
__device__ __forceinline__ uint32_t pack2h(float v0, float v1) {
    uint32_t r;
    asm("cvt.rn.f16x2.f32 %0, %1, %2;" : "=r"(r) : "f"(v1), "f"(v0));
    return r;
}
__device__ __forceinline__ void mma_f16(float* c, const uint4& a, uint32_t b0, uint32_t b1) {
    asm volatile("mma.sync.aligned.m16n8k16.row.col.f32.f16.f16.f32 "
        "{%0,%1,%2,%3}, {%4,%5,%6,%7}, {%8,%9}, {%0,%1,%2,%3};"
        : "+f"(c[0]), "+f"(c[1]), "+f"(c[2]), "+f"(c[3])
        : "r"(a.x), "r"(a.y), "r"(a.z), "r"(a.w), "r"(b0), "r"(b1));
}

// ---------- pack kernel (frag-order fp16 weights, n-tile pairs in 16B) ----------
__global__ void pack_w(const float* __restrict__ W1, const float* __restrict__ W2) {
    int idx = blockIdx.x * blockDim.x + threadIdx.x;   // 0..131071
    if (idx < 98304) {           // W1: kp*512 + n
        int kp = idx >> 9, n = idx & 511, k = kp * 2;
        float v0 = W1[(size_t)k * 512 + n], v1 = W1[(size_t)(k + 1) * 512 + n];
        int chunk = n >> 7, slice = k >> 6;
        int kt = (k & 63) >> 4, reg = (k & 15) >> 3;
        int nt = (n & 127) >> 3, np = nt >> 1, sub = nt & 1;
        int lane = (n & 7) * 4 + ((k & 7) >> 1);
        size_t off = (size_t)(chunk * 6 + slice) * 16384
                   + (size_t)((kt * 8 + np) * 32 + lane) * 16 + sub * 8 + reg * 4;
        *(uint32_t*)(g_W1p + off) = pack2h(v0, v1);
    } else {                     // W2: kp*128 + n
        int j = idx - 98304;
        int kp = j >> 7, n = j & 127, k = kp * 2;
        float v0 = W2[(size_t)k * 128 + n], v1 = W2[(size_t)(k + 1) * 128 + n];
        int chunk = k >> 7, ksl = (k >> 6) & 1;
        int kt = (k & 63) >> 4, reg = (k & 15) >> 3;
        int nt = n >> 3, np = nt >> 1, sub = nt & 1;
        int lane = (n & 7) * 4 + ((k & 7) >> 1);
        size_t off = (size_t)(chunk * 2 + ksl) * 16384
                   + (size_t)((kt * 8 + np) * 32 + lane) * 16 + sub * 8 + reg * 4;
        *(uint32_t*)(g_W2p + off) = pack2h(v0, v1);
    }
}

// ---------- main kernel ----------
__global__ void __launch_bounds__(NTH, 1) edge_mlp_hmma(
    const float* __restrict__ x_i, const float* __restrict__ x_j,
    const float* __restrict__ edge,
    const float* __restrict__ b1, const float* __restrict__ b2,
    const float* __restrict__ gamma, const float* __restrict__ beta,
    float* __restrict__ out)
{
    extern __shared__ char smem[];
    const uint32_t sb = smem_u32(smem);
    const int tid  = threadIdx.x;
    const int w    = tid >> 5, lane = tid & 31;
    const int mband = w >> 2, nband = w & 3;
    const int row0 = blockIdx.x * 128;

    if (tid == 0) { MBAR_INIT(sb + 0, 1); MBAR_INIT(sb + 8, 1); MBAR_INIT(sb + 16, 1); }
    __syncthreads();

    float acc1[2][4][4];
    float acc2[2][4][4];
#pragma unroll
    for (int a = 0; a < 2; a++)
#pragma unroll
        for (int b = 0; b < 4; b++)
#pragma unroll
            for (int cc = 0; cc < 4; cc++) { acc1[a][b][cc] = 0.f; acc2[a][b][cc] = 0.f; }

    int p0 = 0, p1 = 0, pw = 0;

    // conversion-entry geometry for this thread's two entries (e, e+512)
    // entry e: mt=e>>7, kt=(e>>5)&3, ln=e&31 ; rows r0,r0+8 ; cols c0..c0+1, c0+8..c0+9
    const int e0mt = tid >> 7, e0kt = (tid >> 5) & 3, eln = tid & 31;
    const int r0a = e0mt * 16 + (eln >> 2);
    const int c0a = e0kt * 16 + (eln & 3) * 2;
    const int r0b = (tid + 512) >> 7 << 4 | (eln >> 2);          // mt of e+512 = e0mt+4
    const int c0b = c0a;                                         // kt identical for e+512

    // ---- prologue: W1(0) bulk; convert slice 0 (x_i, k 0..63) straight from gmem ----
    if (tid == 0) { MBAR_EXPECT(sb + 0, 16384); bulk_g2s(sb + SM_W10, g_W1p, 16384, sb + 0); }
    {
#pragma unroll
        for (int ee = 0; ee < 2; ee++) {
            int rr = ee ? r0b : r0a;
            const float* base = x_i + (size_t)(row0 + rr) * 128 + c0a;
            float2 v0 = *(const float2*)(base);
            float2 v1 = *(const float2*)(base + 8 * 128);
            float2 v2 = *(const float2*)(base + 8);
            float2 v3 = *(const float2*)(base + 8 * 128 + 8);
            uint4 hv;
            hv.x = pack2h(v0.x, v0.y); hv.y = pack2h(v1.x, v1.y);
            hv.z = pack2h(v2.x, v2.y); hv.w = pack2h(v3.x, v3.y);
            *(uint4*)(smem + SM_A0 + (uint32_t)(tid + ee * 512) * 16) = hv;
        }
    }

#pragma unroll 1
    for (int c = 0; c < 4; c++) {
        if (tid == 0) { MBAR_EXPECT(sb + 16, 32768); bulk_g2s(sb + SM_W2, g_W2p + (size_t)c * 32768, 32768, sb + 16); }

        // ===== GEMM1: 6 k-slices of 64, single-pass fp16 =====
#pragma unroll 1
        for (int sl = 0; sl < 6; sl++) {
            const int s = c * 6 + sl;
            // wait W1 slice s; make A[s&1] conversion + prior MMA completion visible
            if (s & 1) { MBAR_WAIT(sb + 8, p1); p1 ^= 1; }
            else       { MBAR_WAIT(sb + 0, p0); p0 ^= 1; }
            __syncthreads();
            // issue W1(s+1) into the buffer MMA(s-1) just released
            if (tid == 0 && s < 23) {
                uint32_t bar = sb + (((s + 1) & 1) ? 8 : 0);
                uint32_t dst = sb + (((s + 1) & 1) ? SM_W11 : SM_W10);
                MBAR_EXPECT(bar, 16384);
                bulk_g2s(dst, g_W1p + (size_t)(s + 1) * 16384, 16384, bar);
            }
            // prefetch x(s+1) into registers (latency hidden under MMAs)
            float2 pre[8];
            if (s < 23) {
                int ss = s + 1;
                int sm6 = ss % 6;
                const float* xs = (sm6 < 2) ? x_i : (sm6 < 4) ? x_j : edge;
                int koff = (ss & 1) * 64;
#pragma unroll
                for (int ee = 0; ee < 2; ee++) {
                    int rr = ee ? r0b : r0a;
                    const float* base = xs + (size_t)(row0 + rr) * 128 + koff + c0a;
                    pre[ee * 4 + 0] = *(const float2*)(base);
                    pre[ee * 4 + 1] = *(const float2*)(base + 8 * 128);
                    pre[ee * 4 + 2] = *(const float2*)(base + 8);
                    pre[ee * 4 + 3] = *(const float2*)(base + 8 * 128 + 8);
                }
            }
            // MMA slice s
            const char* Ab = smem + ((s & 1) ? SM_A1 : SM_A0);
            const char* Wb = smem + ((s & 1) ? SM_W11 : SM_W10);
#pragma unroll
            for (int kt = 0; kt < 4; kt++) {
                uint4 ah[2];
#pragma unroll
                for (int m = 0; m < 2; m++)
                    ah[m] = *(const uint4*)(Ab + (uint32_t)(((mband * 2 + m) * 4 + kt) * 32 + lane) * 16);
#pragma unroll
                for (int np = 0; np < 2; np++) {
                    int npg = nband * 2 + np;
                    uint4 Bv = *(const uint4*)(Wb + (uint32_t)((kt * 8 + npg) * 32 + lane) * 16);
                    mma_f16(acc1[0][np * 2],     ah[0], Bv.x, Bv.y);
                    mma_f16(acc1[1][np * 2],     ah[1], Bv.x, Bv.y);
                    mma_f16(acc1[0][np * 2 + 1], ah[0], Bv.z, Bv.w);
                    mma_f16(acc1[1][np * 2 + 1], ah[1], Bv.z, Bv.w);
                }
            }
            // convert prefetched x(s+1) -> A[(s+1)&1]
            if (s < 23) {
                char* Ab2 = smem + (((s + 1) & 1) ? SM_A1 : SM_A0);
#pragma unroll
                for (int ee = 0; ee < 2; ee++) {
                    uint4 hv;
                    hv.x = pack2h(pre[ee * 4 + 0].x, pre[ee * 4 + 0].y);
                    hv.y = pack2h(pre[ee * 4 + 1].x, pre[ee * 4 + 1].y);
                    hv.z = pack2h(pre[ee * 4 + 2].x, pre[ee * 4 + 2].y);
                    hv.w = pack2h(pre[ee * 4 + 3].x, pre[ee * 4 + 3].y);
                    *(uint4*)(Ab2 + (uint32_t)(tid + ee * 512) * 16) = hv;
                }
            }
        }

        // ===== SiLU -> h frags (single fp16); GEMM2 over 2 k-slices of 64 =====
#pragma unroll 1
        for (int ksl = 0; ksl < 2; ksl++) {
            if ((nband >> 1) == ksl) {
#pragma unroll
                for (int t = 0; t < 2; t++) {       // ntp pair (2t, 2t+1) -> one STS.128
                    int ntp0 = 2 * t, ntp1 = 2 * t + 1;
                    int colc = nband * 32 + ntp0 * 8 + (lane & 3) * 2;
                    int colg = c * 128 + colc;
                    float b00 = b1[colg],     b01 = b1[colg + 1];
                    float b10 = b1[colg + 8], b11 = b1[colg + 9];
                    int kloc = colc - ksl * 64;
                    int kt_h = kloc >> 4;
#pragma unroll
                    for (int mtp = 0; mtp < 2; mtp++) {
                        uint32_t base = (uint32_t)(((mband * 2 + mtp) * 4 + kt_h) * 32 + lane) * 16;
                        float v0 = acc1[mtp][ntp0][0] + b00;
                        float v1 = acc1[mtp][ntp0][1] + b01;
                        float v2 = acc1[mtp][ntp0][2] + b00;
                        float v3 = acc1[mtp][ntp0][3] + b01;
                        float w0 = acc1[mtp][ntp1][0] + b10;
                        float w1 = acc1[mtp][ntp1][1] + b11;
                        float w2 = acc1[mtp][ntp1][2] + b10;
                        float w3 = acc1[mtp][ntp1][3] + b11;
                        v0 /= (1.0f + __expf(-v0)); v1 /= (1.0f + __expf(-v1));
                        v2 /= (1.0f + __expf(-v2)); v3 /= (1.0f + __expf(-v3));
                        w0 /= (1.0f + __expf(-w0)); w1 /= (1.0f + __expf(-w1));
                        w2 /= (1.0f + __expf(-w2)); w3 /= (1.0f + __expf(-w3));
                        uint4 hv;
                        hv.x = pack2h(v0, v1); hv.y = pack2h(v2, v3);
                        hv.z = pack2h(w0, w1); hv.w = pack2h(w2, w3);
                        *(uint4*)(smem + SM_H + base) = hv;
                    }
                }
            }
            if (ksl == 0) { MBAR_WAIT(sb + 16, pw); pw ^= 1; }
            __syncthreads();

            const char* Hb  = smem + SM_H;
            const char* W2b = smem + SM_W2 + ksl * 16384;
#pragma unroll
            for (int kt = 0; kt < 4; kt++) {
                uint4 ah[2];
#pragma unroll
                for (int m = 0; m < 2; m++)
                    ah[m] = *(const uint4*)(Hb + (uint32_t)(((mband * 2 + m) * 4 + kt) * 32 + lane) * 16);
#pragma unroll
                for (int np = 0; np < 2; np++) {
                    int npg = nband * 2 + np;
                    uint4 Bv = *(const uint4*)(W2b + (uint32_t)((kt * 8 + npg) * 32 + lane) * 16);
                    mma_f16(acc2[0][np * 2],     ah[0], Bv.x, Bv.y);
                    mma_f16(acc2[1][np * 2],     ah[1], Bv.x, Bv.y);
                    mma_f16(acc2[0][np * 2 + 1], ah[0], Bv.z, Bv.w);
                    mma_f16(acc2[1][np * 2 + 1], ah[1], Bv.z, Bv.w);
                }
            }
            __syncthreads();
        }
        // reset acc1 for next chunk
#pragma unroll
        for (int a = 0; a < 2; a++)
#pragma unroll
            for (int b = 0; b < 4; b++)
#pragma unroll
                for (int cc = 0; cc < 4; cc++) acc1[a][b][cc] = 0.f;
    }

    // ===== epilogue: stage acc2+b2, LayerNorm, +edge, store =====
    float* stg = (float*)(smem + SM_A0);   // 128 x 130 fp32 (A/W1/W2 regions dead)
    __syncthreads();
#pragma unroll
    for (int ntp = 0; ntp < 4; ntp++) {
        int col = nband * 32 + ntp * 8 + (lane & 3) * 2;
        float bb0 = b2[col], bb1 = b2[col + 1];
#pragma unroll
        for (int mtp = 0; mtp < 2; mtp++) {
            int row = mband * 32 + mtp * 16 + (lane >> 2);
            float2 v0 = make_float2(acc2[mtp][ntp][0] + bb0, acc2[mtp][ntp][1] + bb1);
            float2 v1 = make_float2(acc2[mtp][ntp][2] + bb0, acc2[mtp][ntp][3] + bb1);
            *(float2*)(stg + row * 130 + col)       = v0;
            *(float2*)(stg + (row + 8) * 130 + col) = v1;
        }
    }
    __syncthreads();
    if (tid < 128) {
        float* rp = stg + tid * 130;
        float s = 0.f, qq = 0.f;
#pragma unroll
        for (int j = 0; j < 128; j += 2) {
            float2 v = *(float2*)(rp + j);
            s += v.x + v.y;
            qq += v.x * v.x + v.y * v.y;
        }
        float mu = s * (1.0f / 128.0f);
        float var = qq * (1.0f / 128.0f) - mu * mu;
        float rs = rsqrtf(var + 1e-5f);
#pragma unroll
        for (int j = 0; j < 128; j += 2) {
            float2 v = *(float2*)(rp + j);
            float2 g = *(const float2*)(gamma + j);
            float2 b = *(const float2*)(beta + j);
            v.x = (v.x - mu) * rs * g.x + b.x;
            v.y = (v.y - mu) * rs * g.y + b.y;
            *(float2*)(rp + j) = v;
        }
    }
    __syncthreads();
#pragma unroll
    for (int it = 0; it < 8; it++) {
        int idx = tid + it * NTH;
        int r = idx >> 5, c4 = idx & 31;
        float2 u0 = *(float2*)(stg + r * 130 + c4 * 4);
        float2 u1 = *(float2*)(stg + r * 130 + c4 * 4 + 2);
        float4 e = *(const float4*)(edge + (size_t)(row0 + r) * 128 + c4 * 4);
        float4 o = make_float4(u0.x + e.x, u0.y + e.y, u1.x + e.z, u1.y + e.w);
        *(float4*)(out + (size_t)(row0 + r) * 128 + c4 * 4) = o;
    }
}

extern "C" void kernel_launch(void* const* d_in, const int* in_sizes, int n_in,
                              void* d_out, int out_size)
{
    const float* x_i   = (const float*)d_in[0];
    const float* x_j   = (const float*)d_in[1];
    const float* edge  = (const float*)d_in[2];
    const float* W1    = (const float*)d_in[3];
    const float* b1    = (const float*)d_in[4];
    const float* W2    = (const float*)d_in[5];
    const float* b2    = (const float*)d_in[6];
    const float* gamma = (const float*)d_in[7];
    const float* beta  = (const float*)d_in[8];
    float* out = (float*)d_out;

    cudaFuncSetAttribute(edge_mlp_hmma, cudaFuncAttributeMaxDynamicSharedMemorySize, SM_TOT);

    pack_w<<<512, 256>>>(W1, W2);
    edge_mlp_hmma<<<NCTA, NTH, SM_TOT>>>(x_i, x_j, edge, b1, b2, gamma, beta, out);
}

// round 8
// speedup vs baseline: 2.5176x; 1.1147x over previous
#include <cuda_runtime.h>
#include <cuda_fp16.h>
#include <cstdint>

#define EN    262144
#define MROWS 64
#define NCTA  (EN / MROWS)   // 4096
#define NTH   256

// ---------- frag-packed fp16 weights (filled once by pack kernel) ----------
// W1: 24 tiles (chunk*6+slice), tile=[64k x 128n] fp16, 16KB
//     entry 16B at ((kt*8+np)*32+lane)*16 = {nt=2np:r0,r1, nt=2np+1:r0,r1}
__device__ __align__(128) unsigned char g_W1p[24 * 16384];   // 384 KB
// W2: 8 tiles (chunk*2+kslice), 16KB, same format
__device__ __align__(128) unsigned char g_W2p[8 * 16384];    // 128 KB

// ---------- smem layout (per 64-row CTA) ----------
#define SM_A0   1024        // A frag buf 0 (8KB)
#define SM_A1   9216
#define SM_W10  17408       // 16KB
#define SM_W11  33792
#define SM_W2   50176       // W2 chunk (2 k-slices, 32KB)
#define SM_H    82944       // h frag (8KB)
#define SM_TOT  91136

// ---------- PTX helpers ----------
__device__ __forceinline__ uint32_t smem_u32(const void* p) {
    uint32_t a;
    asm("{ .reg .u64 t; cvta.to.shared.u64 t, %1; cvt.u32.u64 %0, t; }" : "=r"(a) : "l"(p));
    return a;
}
#define MBAR_INIT(a, n)   asm volatile("mbarrier.init.shared.b64 [%0], %1;" :: "r"(a), "r"(n) : "memory")
#define MBAR_EXPECT(a, b) asm volatile("mbarrier.arrive.expect_tx.shared.b64 _, [%0], %1;" :: "r"(a), "r"(b) : "memory")
#define MBAR_WAIT(a, ph) do { \
    uint32_t _m = (a), _p = (ph), _d; \
    asm volatile("{ .reg .pred p; mbarrier.try_wait.parity.acquire.cta.shared::cta.b64 p, [%1], %2; selp.b32 %0,1,0,p; }" \
        : "=r"(_d) : "r"(_m), "r"(_p) : "memory"); \
    if (!_d) { \
        asm volatile("{ .reg .pred P1; WL_%=: mbarrier.try_wait.parity.acquire.cta.shared::cta.b64 P1, [%0], %1, 0x989680;\n\t" \
                     "@P1 bra.uni WD_%=; bra.uni WL_%=; WD_%=: }" :: "r"(_m), "r"(_p) : "memory"); \
    } } while (0)

__device__ __forceinline__ void bulk_g2s(uint32_t dst, const void* src, uint32_t bytes, uint32_t bar) {
    asm volatile("cp.async.bulk.shared::cluster.global.mbarrier::complete_tx::bytes [%0], [%1], %2, [%3];"
        :: "r"(dst), "l"(src), "r"(bytes), "r"(bar) : "memory");
}
// pack two fp32 -> f16x2, v0 (lower k) in low 16 bits
__device__ __forceinline__ uint32_t pack2h(float v0, float v1) {
    uint32_t r;
    asm("cvt.rn.f16x2.f32 %0, %1, %2;" : "=r"(r) : "f"(v1), "f"(v0));
    return r;
}
__device__ __forceinline__ void mma_f16(float* c, const uint4& a, uint32_t b0, uint32_t b1) {
    asm volatile("mma.sync.aligned.m16n8k16.row.col.f32.f16.f16.f32 "
        "{%0,%1,%2,%3}, {%4,%5,%6,%7}, {%8,%9}, {%0,%1,%2,%3};"
        : "+f"(c[0]), "+f"(c[1]), "+f"(c[2]), "+f"(c[3])
        : "r"(a.x), "r"(a.y), "r"(a.z), "r"(a.w), "r"(b0), "r"(b1));
}

// ---------- pack kernel (frag-order fp16 weights, n-tile pairs in 16B) ----------
__global__ void pack_w(const float* __restrict__ W1, const float* __restrict__ W2) {
    int idx = blockIdx.x * blockDim.x + threadIdx.x;   // 0..131071
    if (idx < 98304) {           // W1: kp*512 + n
        int kp = idx >> 9, n = idx & 511, k = kp * 2;
        float v0 = W1[(size_t)k * 512 + n], v1 = W1[(size_t)(k + 1) * 512 + n];
        int chunk = n >> 7, slice = k >> 6;
        int kt = (k & 63) >> 4, reg = (k & 15) >> 3;
        int nt = (n & 127) >> 3, np = nt >> 1, sub = nt & 1;
        int lane = (n & 7) * 4 + ((k & 7) >> 1);
        size_t off = (size_t)(chunk * 6 + slice) * 16384
                   + (size_t)((kt * 8 + np) * 32 + lane) * 16 + sub * 8 + reg * 4;
        *(uint32_t*)(g_W1p + off) = pack2h(v0, v1);
    } else {                     // W2: kp*128 + n
        int j = idx - 98304;
        int kp = j >> 7, n = j & 127, k = kp * 2;
        float v0 = W2[(size_t)k * 128 + n], v1 = W2[(size_t)(k + 1) * 128 + n];
        int chunk = k >> 7, ksl = (k >> 6) & 1;
        int kt = (k & 63) >> 4, reg = (k & 15) >> 3;
        int nt = n >> 3, np = nt >> 1, sub = nt & 1;
        int lane = (n & 7) * 4 + ((k & 7) >> 1);
        size_t off = (size_t)(chunk * 2 + ksl) * 16384
                   + (size_t)((kt * 8 + np) * 32 + lane) * 16 + sub * 8 + reg * 4;
        *(uint32_t*)(g_W2p + off) = pack2h(v0, v1);
    }
}

// ---------- main kernel: 64 rows / 256 threads / 2 CTAs per SM ----------
__global__ void __launch_bounds__(NTH, 2) edge_mlp_hmma(
    const float* __restrict__ x_i, const float* __restrict__ x_j,
    const float* __restrict__ edge,
    const float* __restrict__ b1, const float* __restrict__ b2,
    const float* __restrict__ gamma, const float* __restrict__ beta,
    float* __restrict__ out)
{
    extern __shared__ char smem[];
    const uint32_t sb = smem_u32(smem);
    const int tid  = threadIdx.x;
    const int w    = tid >> 5, lane = tid & 31;
    const int mband = w >> 2, nband = w & 3;      // 2 mbands x 4 nbands
    const int row0 = blockIdx.x * MROWS;

    if (tid == 0) { MBAR_INIT(sb + 0, 1); MBAR_INIT(sb + 8, 1); MBAR_INIT(sb + 16, 1); }
    __syncthreads();

    float acc1[2][4][4];
    float acc2[2][4][4];
#pragma unroll
    for (int a = 0; a < 2; a++)
#pragma unroll
        for (int b = 0; b < 4; b++)
#pragma unroll
            for (int cc = 0; cc < 4; cc++) { acc1[a][b][cc] = 0.f; acc2[a][b][cc] = 0.f; }

    int p0 = 0, p1 = 0, pw = 0;

    // conversion-entry geometry: thread handles entries e=tid and e=tid+256
    // entry e: mt=e>>7 (0..3), kt=(e>>5)&3, ln=e&31; rows r0,r0+8; cols c0..c0+1,c0+8..c0+9
    const int e0mt = tid >> 7, e0kt = (tid >> 5) & 3, eln = tid & 31;
    const int r0a = e0mt * 16 + (eln >> 2);
    const int r0b = (e0mt + 2) * 16 + (eln >> 2);
    const int c0a = e0kt * 16 + (eln & 3) * 2;

    // ---- prologue: W1(0) bulk; convert slice 0 (x_i, k 0..63) straight from gmem ----
    if (tid == 0) { MBAR_EXPECT(sb + 0, 16384); bulk_g2s(sb + SM_W10, g_W1p, 16384, sb + 0); }
    {
#pragma unroll
        for (int ee = 0; ee < 2; ee++) {
            int rr = ee ? r0b : r0a;
            const float* base = x_i + (size_t)(row0 + rr) * 128 + c0a;
            float2 v0 = *(const float2*)(base);
            float2 v1 = *(const float2*)(base + 8 * 128);
            float2 v2 = *(const float2*)(base + 8);
            float2 v3 = *(const float2*)(base + 8 * 128 + 8);
            uint4 hv;
            hv.x = pack2h(v0.x, v0.y); hv.y = pack2h(v1.x, v1.y);
            hv.z = pack2h(v2.x, v2.y); hv.w = pack2h(v3.x, v3.y);
            *(uint4*)(smem + SM_A0 + (uint32_t)(tid + ee * 256) * 16) = hv;
        }
    }

#pragma unroll 1
    for (int c = 0; c < 4; c++) {
        if (tid == 0) { MBAR_EXPECT(sb + 16, 32768); bulk_g2s(sb + SM_W2, g_W2p + (size_t)c * 32768, 32768, sb + 16); }

        // ===== GEMM1: 6 k-slices of 64, single-pass fp16 =====
#pragma unroll 1
        for (int sl = 0; sl < 6; sl++) {
            const int s = c * 6 + sl;
            // wait W1 slice s; make A[s&1] conversion + prior MMA completion visible
            if (s & 1) { MBAR_WAIT(sb + 8, p1); p1 ^= 1; }
            else       { MBAR_WAIT(sb + 0, p0); p0 ^= 1; }
            __syncthreads();
            // issue W1(s+1) into the buffer MMA(s-1) just released
            if (tid == 0 && s < 23) {
                uint32_t bar = sb + (((s + 1) & 1) ? 8 : 0);
                uint32_t dst = sb + (((s + 1) & 1) ? SM_W11 : SM_W10);
                MBAR_EXPECT(bar, 16384);
                bulk_g2s(dst, g_W1p + (size_t)(s + 1) * 16384, 16384, bar);
            }
            // prefetch x(s+1) into registers (latency hidden under MMAs)
            float2 pre[8];
            if (s < 23) {
                int ss = s + 1;
                int sm6 = ss % 6;
                const float* xs = (sm6 < 2) ? x_i : (sm6 < 4) ? x_j : edge;
                int koff = (ss & 1) * 64;
#pragma unroll
                for (int ee = 0; ee < 2; ee++) {
                    int rr = ee ? r0b : r0a;
                    const float* base = xs + (size_t)(row0 + rr) * 128 + koff + c0a;
                    pre[ee * 4 + 0] = *(const float2*)(base);
                    pre[ee * 4 + 1] = *(const float2*)(base + 8 * 128);
                    pre[ee * 4 + 2] = *(const float2*)(base + 8);
                    pre[ee * 4 + 3] = *(const float2*)(base + 8 * 128 + 8);
                }
            }
            // MMA slice s
            const char* Ab = smem + ((s & 1) ? SM_A1 : SM_A0);
            const char* Wb = smem + ((s & 1) ? SM_W11 : SM_W10);
#pragma unroll
            for (int kt = 0; kt < 4; kt++) {
                uint4 ah[2];
#pragma unroll
                for (int m = 0; m < 2; m++)
                    ah[m] = *(const uint4*)(Ab + (uint32_t)(((mband * 2 + m) * 4 + kt) * 32 + lane) * 16);
#pragma unroll
                for (int np = 0; np < 2; np++) {
                    int npg = nband * 2 + np;
                    uint4 Bv = *(const uint4*)(Wb + (uint32_t)((kt * 8 + npg) * 32 + lane) * 16);
                    mma_f16(acc1[0][np * 2],     ah[0], Bv.x, Bv.y);
                    mma_f16(acc1[1][np * 2],     ah[1], Bv.x, Bv.y);
                    mma_f16(acc1[0][np * 2 + 1], ah[0], Bv.z, Bv.w);
                    mma_f16(acc1[1][np * 2 + 1], ah[1], Bv.z, Bv.w);
                }
            }
            // convert prefetched x(s+1) -> A[(s+1)&1]
            if (s < 23) {
                char* Ab2 = smem + (((s + 1) & 1) ? SM_A1 : SM_A0);
#pragma unroll
                for (int ee = 0; ee < 2; ee++) {
                    uint4 hv;
                    hv.x = pack2h(pre[ee * 4 + 0].x, pre[ee * 4 + 0].y);
                    hv.y = pack2h(pre[ee * 4 + 1].x, pre[ee * 4 + 1].y);
                    hv.z = pack2h(pre[ee * 4 + 2].x, pre[ee * 4 + 2].y);
                    hv.w = pack2h(pre[ee * 4 + 3].x, pre[ee * 4 + 3].y);
                    *(uint4*)(Ab2 + (uint32_t)(tid + ee * 256) * 16) = hv;
                }
            }
        }

        // ===== SiLU -> h frags (single fp16); GEMM2 over 2 k-slices of 64 =====
#pragma unroll 1
        for (int ksl = 0; ksl < 2; ksl++) {
            if ((nband >> 1) == ksl) {
#pragma unroll
                for (int t = 0; t < 2; t++) {       // ntp pair (2t, 2t+1) -> one STS.128
                    int ntp0 = 2 * t, ntp1 = 2 * t + 1;
                    int colc = nband * 32 + ntp0 * 8 + (lane & 3) * 2;
                    int colg = c * 128 + colc;
                    float b00 = b1[colg],     b01 = b1[colg + 1];
                    float b10 = b1[colg + 8], b11 = b1[colg + 9];
                    int kloc = colc - ksl * 64;
                    int kt_h = kloc >> 4;
#pragma unroll
                    for (int mtp = 0; mtp < 2; mtp++) {
                        uint32_t base = (uint32_t)(((mband * 2 + mtp) * 4 + kt_h) * 32 + lane) * 16;
                        float v0 = acc1[mtp][ntp0][0] + b00;
                        float v1 = acc1[mtp][ntp0][1] + b01;
                        float v2 = acc1[mtp][ntp0][2] + b00;
                        float v3 = acc1[mtp][ntp0][3] + b01;
                        float w0 = acc1[mtp][ntp1][0] + b10;
                        float w1 = acc1[mtp][ntp1][1] + b11;
                        float w2 = acc1[mtp][ntp1][2] + b10;
                        float w3 = acc1[mtp][ntp1][3] + b11;
                        v0 /= (1.0f + __expf(-v0)); v1 /= (1.0f + __expf(-v1));
                        v2 /= (1.0f + __expf(-v2)); v3 /= (1.0f + __expf(-v3));
                        w0 /= (1.0f + __expf(-w0)); w1 /= (1.0f + __expf(-w1));
                        w2 /= (1.0f + __expf(-w2)); w3 /= (1.0f + __expf(-w3));
                        uint4 hv;
                        hv.x = pack2h(v0, v1); hv.y = pack2h(v2, v3);
                        hv.z = pack2h(w0, w1); hv.w = pack2h(w2, w3);
                        *(uint4*)(smem + SM_H + base) = hv;
                    }
                }
            }
            if (ksl == 0) { MBAR_WAIT(sb + 16, pw); pw ^= 1; }
            __syncthreads();

            const char* Hb  = smem + SM_H;
            const char* W2b = smem + SM_W2 + ksl * 16384;
#pragma unroll
            for (int kt = 0; kt < 4; kt++) {
                uint4 ah[2];
#pragma unroll
                for (int m = 0; m < 2; m++)
                    ah[m] = *(const uint4*)(Hb + (uint32_t)(((mband * 2 + m) * 4 + kt) * 32 + lane) * 16);
#pragma unroll
                for (int np = 0; np < 2; np++) {
                    int npg = nband * 2 + np;
                    uint4 Bv = *(const uint4*)(W2b + (uint32_t)((kt * 8 + npg) * 32 + lane) * 16);
                    mma_f16(acc2[0][np * 2],     ah[0], Bv.x, Bv.y);
                    mma_f16(acc2[1][np * 2],     ah[1], Bv.x, Bv.y);
                    mma_f16(acc2[0][np * 2 + 1], ah[0], Bv.z, Bv.w);
                    mma_f16(acc2[1][np * 2 + 1], ah[1], Bv.z, Bv.w);
                }
            }
            __syncthreads();
        }
        // reset acc1 for next chunk
#pragma unroll
        for (int a = 0; a < 2; a++)
#pragma unroll
            for (int b = 0; b < 4; b++)
#pragma unroll
                for (int cc = 0; cc < 4; cc++) acc1[a][b][cc] = 0.f;
    }

    // ===== epilogue: stage acc2+b2, LayerNorm, +edge, store =====
    float* stg = (float*)(smem + SM_A0);   // 64 x 130 fp32 (A/W1 regions dead)
    __syncthreads();
#pragma unroll
    for (int ntp = 0; ntp < 4; ntp++) {
        int col = nband * 32 + ntp * 8 + (lane & 3) * 2;
        float bb0 = b2[col], bb1 = b2[col + 1];
#pragma unroll
        for (int mtp = 0; mtp < 2; mtp++) {
            int row = mband * 32 + mtp * 16 + (lane >> 2);
            float2 v0 = make_float2(acc2[mtp][ntp][0] + bb0, acc2[mtp][ntp][1] + bb1);
            float2 v1 = make_float2(acc2[mtp][ntp][2] + bb0, acc2[mtp][ntp][3] + bb1);
            *(float2*)(stg + row * 130 + col)       = v0;
            *(float2*)(stg + (row + 8) * 130 + col) = v1;
        }
    }
    __syncthreads();
    if (tid < MROWS) {
        float* rp = stg + tid * 130;
        float s = 0.f, qq = 0.f;
#pragma unroll
        for (int j = 0; j < 128; j += 2) {
            float2 v = *(float2*)(rp + j);
            s += v.x + v.y;
            qq += v.x * v.x + v.y * v.y;
        }
        float mu = s * (1.0f / 128.0f);
        float var = qq * (1.0f / 128.0f) - mu * mu;
        float rs = rsqrtf(var + 1e-5f);
#pragma unroll
        for (int j = 0; j < 128; j += 2) {
            float2 v = *(float2*)(rp + j);
            float2 g = *(const float2*)(gamma + j);
            float2 b = *(const float2*)(beta + j);
            v.x = (v.x - mu) * rs * g.x + b.x;
            v.y = (v.y - mu) * rs * g.y + b.y;
            *(float2*)(rp + j) = v;
        }
    }
    __syncthreads();
#pragma unroll
    for (int it = 0; it < 8; it++) {
        int idx = tid + it * NTH;
        int r = idx >> 5, c4 = idx & 31;
        float2 u0 = *(float2*)(stg + r * 130 + c4 * 4);
        float2 u1 = *(float2*)(stg + r * 130 + c4 * 4 + 2);
        float4 e = *(const float4*)(edge + (size_t)(row0 + r) * 128 + c4 * 4);
        float4 o = make_float4(u0.x + e.x, u0.y + e.y, u1.x + e.z, u1.y + e.w);
        *(float4*)(out + (size_t)(row0 + r) * 128 + c4 * 4) = o;
    }
}

extern "C" void kernel_launch(void* const* d_in, const int* in_sizes, int n_in,
                              void* d_out, int out_size)
{
    const float* x_i   = (const float*)d_in[0];
    const float* x_j   = (const float*)d_in[1];
    const float* edge  = (const float*)d_in[2];
    const float* W1    = (const float*)d_in[3];
    const float* b1    = (const float*)d_in[4];
    const float* W2    = (const float*)d_in[5];
    const float* b2    = (const float*)d_in[6];
    const float* gamma = (const float*)d_in[7];
    const float* beta  = (const float*)d_in[8];
    float* out = (float*)d_out;

    cudaFuncSetAttribute(edge_mlp_hmma, cudaFuncAttributeMaxDynamicSharedMemorySize, SM_TOT);

    pack_w<<<512, 256>>>(W1, W2);
    edge_mlp_hmma<<<NCTA, NTH, SM_TOT>>>(x_i, x_j, edge, b1, b2, gamma, beta, out);
}

// round 9
// speedup vs baseline: 3.2195x; 1.2788x over previous
#include <cuda_runtime.h>
#include <cuda_fp16.h>
#include <cstdint>

#define EN    262144
#define MROWS 64
#define NCTA  (EN / MROWS)   // 4096
#define NTH   256

// ---------- frag-packed fp16 weights (filled once by pack kernel) ----------
// W1: 24 tiles (chunk*6+slice), tile=[64k x 128n] fp16, 16KB
//     entry 16B at ((kt*8+np)*32+lane)*16 = {nt=2np:r0,r1, nt=2np+1:r0,r1}
__device__ __align__(128) unsigned char g_W1p[24 * 16384];   // 384 KB
// W2: 8 tiles (chunk*2+kslice), 16KB, same format
__device__ __align__(128) unsigned char g_W2p[8 * 16384];    // 128 KB

// ---------- smem layout (per 64-row CTA, 113KB -> 2 CTAs/SM) ----------
#define SM_A    1024        // 6 resident A-frag slices x 8KB = 48KB
#define SM_W10  50176       // W1 tile buf 0 (16KB)
#define SM_W11  66560       // W1 tile buf 1 (16KB)
#define SM_W2   82944       // W2 chunk (2 k-slices, 32KB)
#define SM_H    SM_W11      // H frag (8KB) overlays W11 (idle during GEMM2)
#define SM_TOT  115712

// ---------- PTX helpers ----------
__device__ __forceinline__ uint32_t smem_u32(const void* p) {
    uint32_t a;
    asm("{ .reg .u64 t; cvta.to.shared.u64 t, %1; cvt.u32.u64 %0, t; }" : "=r"(a) : "l"(p));
    return a;
}
#define MBAR_INIT(a, n)   asm volatile("mbarrier.init.shared.b64 [%0], %1;" :: "r"(a), "r"(n) : "memory")
#define MBAR_EXPECT(a, b) asm volatile("mbarrier.arrive.expect_tx.shared.b64 _, [%0], %1;" :: "r"(a), "r"(b) : "memory")
#define MBAR_WAIT(a, ph) do { \
    uint32_t _m = (a), _p = (ph), _d; \
    asm volatile("{ .reg .pred p; mbarrier.try_wait.parity.acquire.cta.shared::cta.b64 p, [%1], %2; selp.b32 %0,1,0,p; }" \
        : "=r"(_d) : "r"(_m), "r"(_p) : "memory"); \
    if (!_d) { \
        asm volatile("{ .reg .pred P1; WL_%=: mbarrier.try_wait.parity.acquire.cta.shared::cta.b64 P1, [%0], %1, 0x989680;\n\t" \
                     "@P1 bra.uni WD_%=; bra.uni WL_%=; WD_%=: }" :: "r"(_m), "r"(_p) : "memory"); \
    } } while (0)

__device__ __forceinline__ void bulk_g2s(uint32_t dst, const void* src, uint32_t bytes, uint32_t bar) {
    asm volatile("cp.async.bulk.shared::cluster.global.mbarrier::complete_tx::bytes [%0], [%1], %2, [%3];"
        :: "r"(dst), "l"(src), "r"(bytes), "r"(bar) : "memory");
}
// pack two fp32 -> f16x2, v0 (lower k) in low 16 bits
__device__ __forceinline__ uint32_t pack2h(float v0, float v1) {
    uint32_t r;
    asm("cvt.rn.f16x2.f32 %0, %1, %2;" : "=r"(r) : "f"(v1), "f"(v0));
    return r;
}
__device__ __forceinline__ void mma_f16(float* c, const uint4& a, uint32_t b0, uint32_t b1) {
    asm volatile("mma.sync.aligned.m16n8k16.row.col.f32.f16.f16.f32 "
        "{%0,%1,%2,%3}, {%4,%5,%6,%7}, {%8,%9}, {%0,%1,%2,%3};"
        : "+f"(c[0]), "+f"(c[1]), "+f"(c[2]), "+f"(c[3])
        : "r"(a.x), "r"(a.y), "r"(a.z), "r"(a.w), "r"(b0), "r"(b1));
}

// ---------- pack kernel (frag-order fp16 weights, n-tile pairs in 16B) ----------
__global__ void pack_w(const float* __restrict__ W1, const float* __restrict__ W2) {
    int idx = blockIdx.x * blockDim.x + threadIdx.x;   // 0..131071
    if (idx < 98304) {           // W1: kp*512 + n
        int kp = idx >> 9, n = idx & 511, k = kp * 2;
        float v0 = W1[(size_t)k * 512 + n], v1 = W1[(size_t)(k + 1) * 512 + n];
        int chunk = n >> 7, slice = k >> 6;
        int kt = (k & 63) >> 4, reg = (k & 15) >> 3;
        int nt = (n & 127) >> 3, np = nt >> 1, sub = nt & 1;
        int lane = (n & 7) * 4 + ((k & 7) >> 1);
        size_t off = (size_t)(chunk * 6 + slice) * 16384
                   + (size_t)((kt * 8 + np) * 32 + lane) * 16 + sub * 8 + reg * 4;
        *(uint32_t*)(g_W1p + off) = pack2h(v0, v1);
    } else {                     // W2: kp*128 + n
        int j = idx - 98304;
        int kp = j >> 7, n = j & 127, k = kp * 2;
        float v0 = W2[(size_t)k * 128 + n], v1 = W2[(size_t)(k + 1) * 128 + n];
        int chunk = k >> 7, ksl = (k >> 6) & 1;
        int kt = (k & 63) >> 4, reg = (k & 15) >> 3;
        int nt = n >> 3, np = nt >> 1, sub = nt & 1;
        int lane = (n & 7) * 4 + ((k & 7) >> 1);
        size_t off = (size_t)(chunk * 2 + ksl) * 16384
                   + (size_t)((kt * 8 + np) * 32 + lane) * 16 + sub * 8 + reg * 4;
        *(uint32_t*)(g_W2p + off) = pack2h(v0, v1);
    }
}

// ---------- main kernel: 64 rows / 256 threads / 2 CTAs per SM ----------
__global__ void __launch_bounds__(NTH, 2) edge_mlp_hmma(
    const float* __restrict__ x_i, const float* __restrict__ x_j,
    const float* __restrict__ edge,
    const float* __restrict__ b1, const float* __restrict__ b2,
    const float* __restrict__ gamma, const float* __restrict__ beta,
    float* __restrict__ out)
{
    extern __shared__ char smem[];
    const uint32_t sb = smem_u32(smem);
    const int tid  = threadIdx.x;
    const int w    = tid >> 5, lane = tid & 31;
    const int mband = w >> 2, nband = w & 3;      // 2 mbands x 4 nbands
    const int row0 = blockIdx.x * MROWS;

    if (tid == 0) { MBAR_INIT(sb + 0, 1); MBAR_INIT(sb + 8, 1); MBAR_INIT(sb + 16, 1); }
    __syncthreads();

    float acc1[2][4][4];
    float acc2[2][4][4];
#pragma unroll
    for (int a = 0; a < 2; a++)
#pragma unroll
        for (int b = 0; b < 4; b++)
#pragma unroll
            for (int cc = 0; cc < 4; cc++) { acc1[a][b][cc] = 0.f; acc2[a][b][cc] = 0.f; }

    int p0 = 0, p1 = 0, pw = 0;

    // conversion-entry geometry: thread handles entries e=tid and e=tid+256 of a slice
    const int e0mt = tid >> 7, e0kt = (tid >> 5) & 3, eln = tid & 31;
    const int r0a = e0mt * 16 + (eln >> 2);
    const int r0b = (e0mt + 2) * 16 + (eln >> 2);
    const int c0a = e0kt * 16 + (eln & 3) * 2;

    // ---- prologue: W1(0) bulk, then convert ALL 6 A-slices (resident) ----
    if (tid == 0) { MBAR_EXPECT(sb + 0, 16384); bulk_g2s(sb + SM_W10, g_W1p, 16384, sb + 0); }
#pragma unroll 1
    for (int ss = 0; ss < 6; ss++) {
        const float* xs = (ss < 2) ? x_i : (ss < 4) ? x_j : edge;
        const int koff = (ss & 1) * 64;
        char* Ab = smem + SM_A + ss * 8192;
        float2 v[8];
#pragma unroll
        for (int ee = 0; ee < 2; ee++) {
            int rr = ee ? r0b : r0a;
            const float* base = xs + (size_t)(row0 + rr) * 128 + koff + c0a;
            v[ee * 4 + 0] = *(const float2*)(base);
            v[ee * 4 + 1] = *(const float2*)(base + 8 * 128);
            v[ee * 4 + 2] = *(const float2*)(base + 8);
            v[ee * 4 + 3] = *(const float2*)(base + 8 * 128 + 8);
        }
#pragma unroll
        for (int ee = 0; ee < 2; ee++) {
            uint4 hv;
            hv.x = pack2h(v[ee * 4 + 0].x, v[ee * 4 + 0].y);
            hv.y = pack2h(v[ee * 4 + 1].x, v[ee * 4 + 1].y);
            hv.z = pack2h(v[ee * 4 + 2].x, v[ee * 4 + 2].y);
            hv.w = pack2h(v[ee * 4 + 3].x, v[ee * 4 + 3].y);
            *(uint4*)(Ab + (uint32_t)(tid + ee * 256) * 16) = hv;
        }
    }
    __syncthreads();   // A frags resident & visible for the whole kernel

#pragma unroll 1
    for (int c = 0; c < 4; c++) {
        // W2 chunk bulk (prior GEMM2 finished at trailing sync)
        if (tid == 0) { MBAR_EXPECT(sb + 16, 32768); bulk_g2s(sb + SM_W2, g_W2p + (size_t)c * 32768, 32768, sb + 16); }

        // ===== GEMM1: 6 k-slices, resident A, W1 double-buffered =====
#pragma unroll 1
        for (int sl = 0; sl < 6; sl++) {
            const int s = c * 6 + sl;
            // wait W1 tile s
            if (s & 1) { MBAR_WAIT(sb + 8, p1); p1 ^= 1; }
            else       { MBAR_WAIT(sb + 0, p0); p0 ^= 1; }
            __syncthreads();   // all warps done MMA(s-1) => buf[(s+1)&1] free
            if (tid == 0 && s < 23) {
                uint32_t bar = sb + (((s + 1) & 1) ? 8 : 0);
                uint32_t dst = sb + (((s + 1) & 1) ? SM_W11 : SM_W10);
                MBAR_EXPECT(bar, 16384);
                bulk_g2s(dst, g_W1p + (size_t)(s + 1) * 16384, 16384, bar);
            }
            const char* Ab = smem + SM_A + sl * 8192;
            const char* Wb = smem + ((s & 1) ? SM_W11 : SM_W10);
#pragma unroll
            for (int kt = 0; kt < 4; kt++) {
                uint4 ah[2];
#pragma unroll
                for (int m = 0; m < 2; m++)
                    ah[m] = *(const uint4*)(Ab + (uint32_t)(((mband * 2 + m) * 4 + kt) * 32 + lane) * 16);
#pragma unroll
                for (int np = 0; np < 2; np++) {
                    int npg = nband * 2 + np;
                    uint4 Bv = *(const uint4*)(Wb + (uint32_t)((kt * 8 + npg) * 32 + lane) * 16);
                    mma_f16(acc1[0][np * 2],     ah[0], Bv.x, Bv.y);
                    mma_f16(acc1[1][np * 2],     ah[1], Bv.x, Bv.y);
                    mma_f16(acc1[0][np * 2 + 1], ah[0], Bv.z, Bv.w);
                    mma_f16(acc1[1][np * 2 + 1], ah[1], Bv.z, Bv.w);
                }
            }
        }

        // ===== SiLU -> H frags (overlay W11); GEMM2 over 2 k-slices =====
        __syncthreads();   // all GEMM1 MMAs done before H overwrites W11
#pragma unroll 1
        for (int ksl = 0; ksl < 2; ksl++) {
            if ((nband >> 1) == ksl) {
#pragma unroll
                for (int t = 0; t < 2; t++) {       // ntp pair (2t,2t+1) -> one STS.128
                    int ntp0 = 2 * t, ntp1 = 2 * t + 1;
                    int colc = nband * 32 + ntp0 * 8 + (lane & 3) * 2;
                    int colg = c * 128 + colc;
                    float b00 = b1[colg],     b01 = b1[colg + 1];
                    float b10 = b1[colg + 8], b11 = b1[colg + 9];
                    int kloc = colc - ksl * 64;
                    int kt_h = kloc >> 4;
#pragma unroll
                    for (int mtp = 0; mtp < 2; mtp++) {
                        uint32_t base = (uint32_t)(((mband * 2 + mtp) * 4 + kt_h) * 32 + lane) * 16;
                        float v0 = acc1[mtp][ntp0][0] + b00;
                        float v1 = acc1[mtp][ntp0][1] + b01;
                        float v2 = acc1[mtp][ntp0][2] + b00;
                        float v3 = acc1[mtp][ntp0][3] + b01;
                        float w0 = acc1[mtp][ntp1][0] + b10;
                        float w1 = acc1[mtp][ntp1][1] + b11;
                        float w2 = acc1[mtp][ntp1][2] + b10;
                        float w3 = acc1[mtp][ntp1][3] + b11;
                        v0 /= (1.0f + __expf(-v0)); v1 /= (1.0f + __expf(-v1));
                        v2 /= (1.0f + __expf(-v2)); v3 /= (1.0f + __expf(-v3));
                        w0 /= (1.0f + __expf(-w0)); w1 /= (1.0f + __expf(-w1));
                        w2 /= (1.0f + __expf(-w2)); w3 /= (1.0f + __expf(-w3));
                        uint4 hv;
                        hv.x = pack2h(v0, v1); hv.y = pack2h(v2, v3);
                        hv.z = pack2h(w0, w1); hv.w = pack2h(w2, w3);
                        *(uint4*)(smem + SM_H + base) = hv;
                    }
                }
            }
            if (ksl == 0) { MBAR_WAIT(sb + 16, pw); pw ^= 1; }
            __syncthreads();

            const char* Hb  = smem + SM_H;
            const char* W2b = smem + SM_W2 + ksl * 16384;
#pragma unroll
            for (int kt = 0; kt < 4; kt++) {
                uint4 ah[2];
#pragma unroll
                for (int m = 0; m < 2; m++)
                    ah[m] = *(const uint4*)(Hb + (uint32_t)(((mband * 2 + m) * 4 + kt) * 32 + lane) * 16);
#pragma unroll
                for (int np = 0; np < 2; np++) {
                    int npg = nband * 2 + np;
                    uint4 Bv = *(const uint4*)(W2b + (uint32_t)((kt * 8 + npg) * 32 + lane) * 16);
                    mma_f16(acc2[0][np * 2],     ah[0], Bv.x, Bv.y);
                    mma_f16(acc2[1][np * 2],     ah[1], Bv.x, Bv.y);
                    mma_f16(acc2[0][np * 2 + 1], ah[0], Bv.z, Bv.w);
                    mma_f16(acc2[1][np * 2 + 1], ah[1], Bv.z, Bv.w);
                }
            }
            __syncthreads();   // H reads done before next ksl / chunk overwrites
        }
        // reset acc1 for next chunk
#pragma unroll
        for (int a = 0; a < 2; a++)
#pragma unroll
            for (int b = 0; b < 4; b++)
#pragma unroll
                for (int cc = 0; cc < 4; cc++) acc1[a][b][cc] = 0.f;
    }

    // ===== epilogue: stage acc2+b2 (overlay A region), LayerNorm, +edge, store =====
    float* stg = (float*)(smem + SM_A);   // 64 x 130 fp32 = 33.3KB (A region dead)
#pragma unroll
    for (int ntp = 0; ntp < 4; ntp++) {
        int col = nband * 32 + ntp * 8 + (lane & 3) * 2;
        float bb0 = b2[col], bb1 = b2[col + 1];
#pragma unroll
        for (int mtp = 0; mtp < 2; mtp++) {
            int row = mband * 32 + mtp * 16 + (lane >> 2);
            float2 v0 = make_float2(acc2[mtp][ntp][0] + bb0, acc2[mtp][ntp][1] + bb1);
            float2 v1 = make_float2(acc2[mtp][ntp][2] + bb0, acc2[mtp][ntp][3] + bb1);
            *(float2*)(stg + row * 130 + col)       = v0;
            *(float2*)(stg + (row + 8) * 130 + col) = v1;
        }
    }
    __syncthreads();
    if (tid < MROWS) {
        float* rp = stg + tid * 130;
        float s = 0.f, qq = 0.f;
#pragma unroll
        for (int j = 0; j < 128; j += 2) {
            float2 v = *(float2*)(rp + j);
            s += v.x + v.y;
            qq += v.x * v.x + v.y * v.y;
        }
        float mu = s * (1.0f / 128.0f);
        float var = qq * (1.0f / 128.0f) - mu * mu;
        float rs = rsqrtf(var + 1e-5f);
#pragma unroll
        for (int j = 0; j < 128; j += 2) {
            float2 v = *(float2*)(rp + j);
            float2 g = *(const float2*)(gamma + j);
            float2 b = *(const float2*)(beta + j);
            v.x = (v.x - mu) * rs * g.x + b.x;
            v.y = (v.y - mu) * rs * g.y + b.y;
            *(float2*)(rp + j) = v;
        }
    }
    __syncthreads();
#pragma unroll
    for (int it = 0; it < 8; it++) {
        int idx = tid + it * NTH;
        int r = idx >> 5, c4 = idx & 31;
        float2 u0 = *(float2*)(stg + r * 130 + c4 * 4);
        float2 u1 = *(float2*)(stg + r * 130 + c4 * 4 + 2);
        float4 e = *(const float4*)(edge + (size_t)(row0 + r) * 128 + c4 * 4);
        float4 o = make_float4(u0.x + e.x, u0.y + e.y, u1.x + e.z, u1.y + e.w);
        *(float4*)(out + (size_t)(row0 + r) * 128 + c4 * 4) = o;
    }
}

extern "C" void kernel_launch(void* const* d_in, const int* in_sizes, int n_in,
                              void* d_out, int out_size)
{
    const float* x_i   = (const float*)d_in[0];
    const float* x_j   = (const float*)d_in[1];
    const float* edge  = (const float*)d_in[2];
    const float* W1    = (const float*)d_in[3];
    const float* b1    = (const float*)d_in[4];
    const float* W2    = (const float*)d_in[5];
    const float* b2    = (const float*)d_in[6];
    const float* gamma = (const float*)d_in[7];
    const float* beta  = (const float*)d_in[8];
    float* out = (float*)d_out;

    cudaFuncSetAttribute(edge_mlp_hmma, cudaFuncAttributeMaxDynamicSharedMemorySize, SM_TOT);

    pack_w<<<512, 256>>>(W1, W2);
    edge_mlp_hmma<<<NCTA, NTH, SM_TOT>>>(x_i, x_j, edge, b1, b2, gamma, beta, out);
}